// round 9
// baseline (speedup 1.0000x reference)
#include <cuda_runtime.h>
#include <math.h>

// Problem constants (match reference)
#define BB 8
#define HH 256
#define WW 256
#define RR 2                        // output rows per block
#define HALO 4                      // column window radius (exactness-checked)
#define DROWS (RR + 2 * HALO)       // decoded rows per block (10)
#define NBLK (BB * (HH / RR))       // 1024 blocks

// ---------------------------------------------------------------------------
// Scratch (device globals — no allocation allowed)
// ---------------------------------------------------------------------------
__device__ double d_partials[NBLK][4];   // {sum p*dist, sum p*t, sum p*p, sum t*t}
__device__ int g_fin;                    // finalize election counter (self-resetting)

// Exact distance to nearest set (inv=false) / clear (inv=true) bit in a
// 256-bit row mask. Returns squared distance (1e10 if none == reference INF).
// Fallback-only.
__device__ __forceinline__ float exact_dist2(const unsigned* m, int i, bool inv) {
    const int wi = i >> 5, bi = i & 31;
    const unsigned mw = inv ? ~m[wi] : m[wi];
    const unsigned lowmask = (2u << bi) - 1u;
    const unsigned himask  = ~((1u << bi) - 1u);
    unsigned wl = mw & lowmask;
    int dl = 100000;
    if (wl) dl = bi - (31 - __clz(wl));
    else {
        for (int k = wi - 1; k >= 0; --k) {
            const unsigned mk = inv ? ~m[k] : m[k];
            if (mk) { dl = i - (k * 32 + 31 - __clz(mk)); break; }
        }
    }
    unsigned wr = mw & himask;
    int dr = 100000;
    if (wr) dr = (__ffs(wr) - 1) - bi;
    else {
        for (int k = wi + 1; k < 8; ++k) {
            const unsigned mk = inv ? ~m[k] : m[k];
            if (mk) { dr = (k * 32 + __ffs(mk) - 1) - i; break; }
        }
    }
    const int d = min(dl, dr);
    return (d >= 1000) ? 1e10f : (float)(d * d);
}

// ---------------------------------------------------------------------------
// Thread = column, block = 2 output rows of one image (1024 blocks).
// dist_map(p) = distance to nearest OPPOSITE-class pixel (one EDT per pixel).
// Ballot-built bit rows; one window extraction per row feeding both class
// distances; per-output class-selected windowed min-plus (K=4) with
// exactness check + exact fallback; fused sigmoid + partials; last-block
// deterministic finalize.
// ---------------------------------------------------------------------------
__global__ __launch_bounds__(WW) void fused(const float* __restrict__ pred,
                                            const float* __restrict__ target,
                                            const int* __restrict__ fl_ptr,
                                            float* __restrict__ out) {
    const int blk  = blockIdx.x;
    const int tid  = threadIdx.x;          // column x
    const int warp = tid >> 5;
    const int lane = tid & 31;

    const int b  = blk >> 7;               // image  (128 blocks per image)
    const int y0 = (blk & 127) * RR;       // first output row
    const int base = b * HH * WW;
    const int x = tid;

    __shared__ unsigned sbits[DROWS][8];   // decoded-row bit masks
    __shared__ unsigned sfull[HH][8];      // fallback-only: full-image bit rows
    __shared__ float rs[8][4];
    __shared__ double fg[8][2];
    __shared__ int s_last;

    // ---- Hoisted global loads ----------------------------------------------
    const int fl = *fl_ptr;
    float pv[RR];
#pragma unroll
    for (int i = 0; i < RR; ++i) pv[i] = pred[base + (y0 + i) * WW + x];

    // ---- ballot-build DROWS bit rows (coalesced target reads) --------------
#pragma unroll
    for (int j = 0; j < DROWS; ++j) {
        const int rj = y0 - HALO + j;
        if (rj >= 0 && rj < HH) {
            const float t = target[base + rj * WW + (warp << 5) + lane];
            const unsigned bal = __ballot_sync(0xffffffffu, t > 0.5f);
            if (lane == 0) sbits[j][warp] = bal;
        }
    }
    __syncthreads();

    // ---- per-column window extraction setup --------------------------------
    const int sh  = x - 5;                 // window start bit (may be <0)
    const int wiw = sh >> 5;               // valid only when x >= 5
    const int shr = sh & 31;
    unsigned vm = 0x7FFu;
    if (x < 5)   vm &= (0x7FFu << (5 - x));
    if (x > 250) vm &= (0x7FFu >> (x - 250));

    // ---- decode row distances (both classes from one extraction) -----------
    float da[DROWS], db[DROWS];            // dist^2 to nearest 1 / nearest 0
#pragma unroll
    for (int j = 0; j < DROWS; ++j) {
        const int rj = y0 - HALO + j;
        if (rj >= 0 && rj < HH) {
            unsigned win;
            if (x >= 5) {
                const unsigned lo = sbits[j][wiw];
                const unsigned hi = (wiw < 7) ? sbits[j][wiw + 1] : 0u;
                win = __funnelshift_r(lo, hi, shr) & 0x7FFu;
            } else {
                win = (sbits[j][0] << (5 - x)) & 0x7FFu;
            }
            unsigned wm = win & vm;
            unsigned l5 = wm & 0x1Fu, r5 = wm >> 6;
            int dl = __clz(l5) - 26;              // l5==0 -> 6
            int fr = __ffs(r5);
            int dr = fr ? fr : 6;
            int d  = ((wm >> 5) & 1u) ? 0 : min(dl, dr);
            da[j] = (float)(d * d);               // 36 == clamped (>=6)
            wm = (~win) & vm;
            l5 = wm & 0x1Fu; r5 = wm >> 6;
            dl = __clz(l5) - 26;
            fr = __ffs(r5);
            dr = fr ? fr : 6;
            d  = ((wm >> 5) & 1u) ? 0 : min(dl, dr);
            db[j] = (float)(d * d);
        } else { da[j] = 1e18f; db[j] = 1e18f; }
    }

    // ---- per-output class bit + selected windowed min-plus -----------------
    int tbit[RR];
    float m[RR];
#pragma unroll
    for (int i = 0; i < RR; ++i) {
        tbit[i] = (sbits[i + HALO][warp] >> lane) & 1u;
        // pixel class 1 -> need dist to nearest 0 (db); class 0 -> da.
        float v0 = tbit[i] ? db[i]     : da[i];
        float v1 = tbit[i] ? db[i + 1] : da[i + 1];
        float v2 = tbit[i] ? db[i + 2] : da[i + 2];
        float v3 = tbit[i] ? db[i + 3] : da[i + 3];
        float v4 = tbit[i] ? db[i + 4] : da[i + 4];
        float v5 = tbit[i] ? db[i + 5] : da[i + 5];
        float v6 = tbit[i] ? db[i + 6] : da[i + 6];
        float v7 = tbit[i] ? db[i + 7] : da[i + 7];
        float v8 = tbit[i] ? db[i + 8] : da[i + 8];
        const float p1 = fminf(v3, v5) + 1.0f;
        const float p2 = fminf(v2, v6) + 4.0f;
        const float p3 = fminf(v1, v7) + 9.0f;
        const float p4 = fminf(v0, v8) + 16.0f;
        m[i] = fminf(fminf(fminf(p1, p2), fminf(p3, p4)), v4);
    }

    // ---- Exactness: valid iff every selected windowed min <= 25 ------------
    float maxr = fmaxf(m[0], m[1]);
    const int need_full = __syncthreads_or(maxr > 25.0f);
    if (need_full) {
        // Exact full-image fallback (deterministic; ~never executes).
        for (int r = 0; r < HH; ++r) {
            const float t = target[base + r * WW + (warp << 5) + lane];
            const unsigned bal = __ballot_sync(0xffffffffu, t > 0.5f);
            if (lane == 0) sfull[r][warp] = bal;
        }
        __syncthreads();
#pragma unroll
        for (int i = 0; i < RR; ++i) m[i] = 3.0e38f;
        for (int r = 0; r < HH; ++r) {
            const float d1 = exact_dist2(sfull[r], x, false);
            const float d0 = exact_dist2(sfull[r], x, true);
#pragma unroll
            for (int i = 0; i < RR; ++i) {
                const float dy = (float)((y0 + i - r) * (y0 + i - r));
                const float dv = tbit[i] ? d0 : d1;
                m[i] = fminf(m[i], dv + dy);
            }
        }
    }

    // ---- Epilogue: sigmoid + partial sums ----------------------------------
    float s_pd = 0.0f, s_pt = 0.0f, s_pp = 0.0f;
    int s_tt = 0;
#pragma unroll
    for (int i = 0; i < RR; ++i) {
        float p = pv[i];
        if (fl) p = __fdividef(1.0f, 1.0f + __expf(-p));
        s_pd += p * sqrtf(m[i]);       // dist_map = sqrt(selected min)
        s_pp += p * p;
        if (tbit[i]) { s_pt += p; s_tt += 1; }
    }
    float s_ttf = (float)s_tt;

#pragma unroll
    for (int off = 16; off > 0; off >>= 1) {
        s_pd  += __shfl_down_sync(0xffffffffu, s_pd,  off);
        s_pt  += __shfl_down_sync(0xffffffffu, s_pt,  off);
        s_pp  += __shfl_down_sync(0xffffffffu, s_pp,  off);
        s_ttf += __shfl_down_sync(0xffffffffu, s_ttf, off);
    }
    if (lane == 0) {
        rs[warp][0] = s_pd; rs[warp][1] = s_pt;
        rs[warp][2] = s_pp; rs[warp][3] = s_ttf;
    }
    __syncthreads();

    if (tid == 0) {
        double a0 = 0.0, a1 = 0.0, a2 = 0.0, a3 = 0.0;
#pragma unroll
        for (int w = 0; w < 8; ++w) {
            a0 += (double)rs[w][0]; a1 += (double)rs[w][1];
            a2 += (double)rs[w][2]; a3 += (double)rs[w][3];
        }
        d_partials[blk][0] = a0; d_partials[blk][1] = a1;
        d_partials[blk][2] = a2; d_partials[blk][3] = a3;
        __threadfence();
        const int old = atomicAdd(&g_fin, 1);
        s_last = (old == NBLK - 1);
    }
    __syncthreads();
    if (!s_last) return;

    // ---- last block: deterministic finalize --------------------------------
    __threadfence();
    {
        const int g = warp;                // one warp per image (8 images)
        const int s = g * 128 + lane;      // 128 partials per image
        double v0 = 0.0, v1 = 0.0, v2 = 0.0, v3 = 0.0;
#pragma unroll
        for (int q = 0; q < 4; ++q) {
            v0 += d_partials[s + q * 32][0];
            v1 += d_partials[s + q * 32][1];
            v2 += d_partials[s + q * 32][2];
            v3 += d_partials[s + q * 32][3];
        }
#pragma unroll
        for (int off = 16; off > 0; off >>= 1) {
            v0 += __shfl_down_sync(0xffffffffu, v0, off);
            v1 += __shfl_down_sync(0xffffffffu, v1, off);
            v2 += __shfl_down_sync(0xffffffffu, v2, off);
            v3 += __shfl_down_sync(0xffffffffu, v3, off);
        }
        if (lane == 0) {
            const double eps = 1e-6;
            fg[g][0] = v0;                                        // boundary sum
            fg[g][1] = 1.0 - (2.0 * v1 + eps) / (v2 + v3 + eps);  // dice term
        }
    }
    __syncthreads();
    if (tid == 0) {
        double bl = 0.0, dl = 0.0;
#pragma unroll
        for (int g = 0; g < BB; ++g) { bl += fg[g][0]; dl += fg[g][1]; }
        dl /= (double)BB;
        bl /= (double)(BB * HH * WW);
        out[0] = (float)(dl + bl);  // ALPHA = BETA = 1
        g_fin = 0;                  // reset for next (graph) replay
        __threadfence();
    }
}

// ---------------------------------------------------------------------------
extern "C" void kernel_launch(void* const* d_in, const int* in_sizes, int n_in,
                              void* d_out, int out_size) {
    const float* pred   = (const float*)d_in[0];
    const float* target = (const float*)d_in[1];
    const int*   fl     = (const int*)d_in[2];
    float* out = (float*)d_out;

    fused<<<NBLK, WW>>>(pred, target, fl, out);
}

// round 10
// speedup vs baseline: 1.2333x; 1.2333x over previous
#include <cuda_runtime.h>
#include <math.h>

// Problem constants (match reference)
#define BB 8
#define HH 256
#define WW 256
#define RR 4                        // output rows per block
#define HALO 4                      // column window radius (exactness-checked)
#define DROWS (RR + 2 * HALO)       // decoded rows per block (12)
#define NBLK (BB * (HH / RR))       // 512 blocks

// ---------------------------------------------------------------------------
// Scratch (device globals — no allocation allowed)
// ---------------------------------------------------------------------------
__device__ double d_partials[NBLK][4];   // {sum p*dist, sum p*t, sum p*p, sum t*t}
__device__ int g_fin;                    // finalize election counter (self-resetting)

// Exact distance to nearest set (inv=false) / clear (inv=true) bit in a
// 256-bit row mask. Returns squared distance (1e10 if none == reference INF).
// Fallback-only.
__device__ __forceinline__ float exact_dist2(const unsigned* m, int i, bool inv) {
    const int wi = i >> 5, bi = i & 31;
    const unsigned mw = inv ? ~m[wi] : m[wi];
    const unsigned lowmask = (2u << bi) - 1u;
    const unsigned himask  = ~((1u << bi) - 1u);
    unsigned wl = mw & lowmask;
    int dl = 100000;
    if (wl) dl = bi - (31 - __clz(wl));
    else {
        for (int k = wi - 1; k >= 0; --k) {
            const unsigned mk = inv ? ~m[k] : m[k];
            if (mk) { dl = i - (k * 32 + 31 - __clz(mk)); break; }
        }
    }
    unsigned wr = mw & himask;
    int dr = 100000;
    if (wr) dr = (__ffs(wr) - 1) - bi;
    else {
        for (int k = wi + 1; k < 8; ++k) {
            const unsigned mk = inv ? ~m[k] : m[k];
            if (mk) { dr = (k * 32 + __ffs(mk) - 1) - i; break; }
        }
    }
    const int d = min(dl, dr);
    return (d >= 1000) ? 1e10f : (float)(d * d);
}

// ---------------------------------------------------------------------------
// Thread = column, block = 4 output rows of one image (512 blocks).
// dist_map(p) = distance to nearest OPPOSITE-class pixel (one EDT per pixel).
// Ballot-built bit rows; one window extraction per row feeding both class
// distances; per-output class-selected single windowed min-plus (K=4) with
// exactness check + exact fallback; fused sigmoid + partials; last-block
// deterministic finalize.
// ---------------------------------------------------------------------------
__global__ __launch_bounds__(WW) void fused(const float* __restrict__ pred,
                                            const float* __restrict__ target,
                                            const int* __restrict__ fl_ptr,
                                            float* __restrict__ out) {
    const int blk  = blockIdx.x;
    const int tid  = threadIdx.x;          // column x
    const int warp = tid >> 5;
    const int lane = tid & 31;

    const int b  = blk >> 6;               // image  (64 blocks per image)
    const int y0 = (blk & 63) * RR;        // first output row
    const int base = b * HH * WW;
    const int x = tid;

    __shared__ unsigned sbits[DROWS][8];   // decoded-row bit masks
    __shared__ unsigned sfull[HH][8];      // fallback-only: full-image bit rows
    __shared__ float rs[8][4];
    __shared__ double fg[8][2];
    __shared__ int s_last;

    // ---- Hoisted global loads ----------------------------------------------
    const int fl = *fl_ptr;
    float pv[RR];
#pragma unroll
    for (int i = 0; i < RR; ++i) pv[i] = pred[base + (y0 + i) * WW + x];

    // ---- ballot-build DROWS bit rows (coalesced target reads) --------------
#pragma unroll
    for (int j = 0; j < DROWS; ++j) {
        const int rj = y0 - HALO + j;
        if (rj >= 0 && rj < HH) {
            const float t = target[base + rj * WW + (warp << 5) + lane];
            const unsigned bal = __ballot_sync(0xffffffffu, t > 0.5f);
            if (lane == 0) sbits[j][warp] = bal;
        }
    }
    __syncthreads();

    // ---- per-column window extraction setup --------------------------------
    const int sh  = x - 5;                 // window start bit (may be <0)
    const int wiw = sh >> 5;               // valid only when x >= 5
    const int shr = sh & 31;
    unsigned vm = 0x7FFu;
    if (x < 5)   vm &= (0x7FFu << (5 - x));
    if (x > 250) vm &= (0x7FFu >> (x - 250));

    // ---- decode row distances (both classes from one extraction) -----------
    float da[DROWS], db[DROWS];            // dist^2 to nearest 1 / nearest 0
#pragma unroll
    for (int j = 0; j < DROWS; ++j) {
        const int rj = y0 - HALO + j;
        if (rj >= 0 && rj < HH) {
            unsigned win;
            if (x >= 5) {
                const unsigned lo = sbits[j][wiw];
                const unsigned hi = (wiw < 7) ? sbits[j][wiw + 1] : 0u;
                win = __funnelshift_r(lo, hi, shr) & 0x7FFu;
            } else {
                win = (sbits[j][0] << (5 - x)) & 0x7FFu;
            }
            unsigned wm = win & vm;
            unsigned l5 = wm & 0x1Fu, r5 = wm >> 6;
            int dl = __clz(l5) - 26;              // l5==0 -> 6
            int fr = __ffs(r5);
            int dr = fr ? fr : 6;
            int d  = ((wm >> 5) & 1u) ? 0 : min(dl, dr);
            da[j] = (float)(d * d);               // 36 == clamped (>=6)
            wm = (~win) & vm;
            l5 = wm & 0x1Fu; r5 = wm >> 6;
            dl = __clz(l5) - 26;
            fr = __ffs(r5);
            dr = fr ? fr : 6;
            d  = ((wm >> 5) & 1u) ? 0 : min(dl, dr);
            db[j] = (float)(d * d);
        } else { da[j] = 1e18f; db[j] = 1e18f; }
    }

    // ---- per-output class bit + selected single windowed min-plus ----------
    int tbit[RR];
    float m[RR];
#pragma unroll
    for (int i = 0; i < RR; ++i) {
        tbit[i] = (sbits[i + HALO][warp] >> lane) & 1u;
        // pixel class 1 -> need dist to nearest 0 (db); class 0 -> da.
        const float v0 = tbit[i] ? db[i]     : da[i];
        const float v1 = tbit[i] ? db[i + 1] : da[i + 1];
        const float v2 = tbit[i] ? db[i + 2] : da[i + 2];
        const float v3 = tbit[i] ? db[i + 3] : da[i + 3];
        const float v4 = tbit[i] ? db[i + 4] : da[i + 4];
        const float v5 = tbit[i] ? db[i + 5] : da[i + 5];
        const float v6 = tbit[i] ? db[i + 6] : da[i + 6];
        const float v7 = tbit[i] ? db[i + 7] : da[i + 7];
        const float v8 = tbit[i] ? db[i + 8] : da[i + 8];
        const float p1 = fminf(v3, v5) + 1.0f;
        const float p2 = fminf(v2, v6) + 4.0f;
        const float p3 = fminf(v1, v7) + 9.0f;
        const float p4 = fminf(v0, v8) + 16.0f;
        m[i] = fminf(fminf(fminf(p1, p2), fminf(p3, p4)), v4);
    }

    // ---- Exactness: valid iff every selected windowed min <= 25 ------------
    float maxr = fmaxf(fmaxf(m[0], m[1]), fmaxf(m[2], m[3]));
    const int need_full = __syncthreads_or(maxr > 25.0f);
    if (need_full) {
        // Exact full-image fallback (deterministic; ~never executes).
        for (int r = 0; r < HH; ++r) {
            const float t = target[base + r * WW + (warp << 5) + lane];
            const unsigned bal = __ballot_sync(0xffffffffu, t > 0.5f);
            if (lane == 0) sfull[r][warp] = bal;
        }
        __syncthreads();
#pragma unroll
        for (int i = 0; i < RR; ++i) m[i] = 3.0e38f;
        for (int r = 0; r < HH; ++r) {
            const float d1 = exact_dist2(sfull[r], x, false);
            const float d0 = exact_dist2(sfull[r], x, true);
#pragma unroll
            for (int i = 0; i < RR; ++i) {
                const float dy = (float)((y0 + i - r) * (y0 + i - r));
                const float dv = tbit[i] ? d0 : d1;
                m[i] = fminf(m[i], dv + dy);
            }
        }
    }

    // ---- Epilogue: sigmoid + partial sums ----------------------------------
    float s_pd = 0.0f, s_pt = 0.0f, s_pp = 0.0f;
    int s_tt = 0;
#pragma unroll
    for (int i = 0; i < RR; ++i) {
        float p = pv[i];
        if (fl) p = __fdividef(1.0f, 1.0f + __expf(-p));
        s_pd += p * sqrtf(m[i]);       // dist_map = sqrt(selected min)
        s_pp += p * p;
        if (tbit[i]) { s_pt += p; s_tt += 1; }
    }
    float s_ttf = (float)s_tt;

#pragma unroll
    for (int off = 16; off > 0; off >>= 1) {
        s_pd  += __shfl_down_sync(0xffffffffu, s_pd,  off);
        s_pt  += __shfl_down_sync(0xffffffffu, s_pt,  off);
        s_pp  += __shfl_down_sync(0xffffffffu, s_pp,  off);
        s_ttf += __shfl_down_sync(0xffffffffu, s_ttf, off);
    }
    if (lane == 0) {
        rs[warp][0] = s_pd; rs[warp][1] = s_pt;
        rs[warp][2] = s_pp; rs[warp][3] = s_ttf;
    }
    __syncthreads();

    if (tid == 0) {
        double a0 = 0.0, a1 = 0.0, a2 = 0.0, a3 = 0.0;
#pragma unroll
        for (int w = 0; w < 8; ++w) {
            a0 += (double)rs[w][0]; a1 += (double)rs[w][1];
            a2 += (double)rs[w][2]; a3 += (double)rs[w][3];
        }
        d_partials[blk][0] = a0; d_partials[blk][1] = a1;
        d_partials[blk][2] = a2; d_partials[blk][3] = a3;
        __threadfence();
        const int old = atomicAdd(&g_fin, 1);
        s_last = (old == NBLK - 1);
    }
    __syncthreads();
    if (!s_last) return;

    // ---- last block: deterministic finalize --------------------------------
    __threadfence();
    {
        const int g = warp;                // one warp per image (8 images)
        const int s = g * 64 + lane;       // 64 partials per image
        double v0 = d_partials[s][0] + d_partials[s + 32][0];
        double v1 = d_partials[s][1] + d_partials[s + 32][1];
        double v2 = d_partials[s][2] + d_partials[s + 32][2];
        double v3 = d_partials[s][3] + d_partials[s + 32][3];
#pragma unroll
        for (int off = 16; off > 0; off >>= 1) {
            v0 += __shfl_down_sync(0xffffffffu, v0, off);
            v1 += __shfl_down_sync(0xffffffffu, v1, off);
            v2 += __shfl_down_sync(0xffffffffu, v2, off);
            v3 += __shfl_down_sync(0xffffffffu, v3, off);
        }
        if (lane == 0) {
            const double eps = 1e-6;
            fg[g][0] = v0;                                        // boundary sum
            fg[g][1] = 1.0 - (2.0 * v1 + eps) / (v2 + v3 + eps);  // dice term
        }
    }
    __syncthreads();
    if (tid == 0) {
        double bl = 0.0, dl = 0.0;
#pragma unroll
        for (int g = 0; g < BB; ++g) { bl += fg[g][0]; dl += fg[g][1]; }
        dl /= (double)BB;
        bl /= (double)(BB * HH * WW);
        out[0] = (float)(dl + bl);  // ALPHA = BETA = 1
        g_fin = 0;                  // reset for next (graph) replay
        __threadfence();
    }
}

// ---------------------------------------------------------------------------
extern "C" void kernel_launch(void* const* d_in, const int* in_sizes, int n_in,
                              void* d_out, int out_size) {
    const float* pred   = (const float*)d_in[0];
    const float* target = (const float*)d_in[1];
    const int*   fl     = (const int*)d_in[2];
    float* out = (float*)d_out;

    fused<<<NBLK, WW>>>(pred, target, fl, out);
}

// round 11
// speedup vs baseline: 1.5298x; 1.2404x over previous
#include <cuda_runtime.h>
#include <math.h>

// Problem constants (match reference)
#define BB 8
#define HH 256
#define WW 256
#define RR 8                        // output rows per block
#define NG 2                        // row groups (thread z-split)
#define RPG (RR / NG)               // output rows per thread (4)
#define DR 16                       // decoded rows per block (RR + 2*4)
#define DPT (DR / NG)               // decoded rows per thread (8)
#define NBLK (BB * (HH / RR))       // 256 blocks
#define NTH  (WW * NG)              // 512 threads
#define PAD_PAIR 0x00240024u        // 36 | 36<<16  (>25 -> can only force fallback)

typedef unsigned u32;

// ---------------------------------------------------------------------------
// Scratch (device globals — no allocation allowed)
// ---------------------------------------------------------------------------
__device__ double d_partials[NBLK][4];   // {sum p*dist, sum p*t, sum p*p, sum t*t}
__device__ int g_fin;                    // finalize election counter (self-resetting)

// Exact squared distance to nearest set (inv=false) / clear (inv=true) bit in
// a 256-bit row mask (1e10 if none == reference INF). Fallback-only.
__device__ __forceinline__ float exact_dist2(const u32* m, int i, bool inv) {
    const int wi = i >> 5, bi = i & 31;
    const u32 mw = inv ? ~m[wi] : m[wi];
    const u32 lowmask = (2u << bi) - 1u;
    const u32 himask  = ~((1u << bi) - 1u);
    u32 wl = mw & lowmask;
    int dl = 100000;
    if (wl) dl = bi - (31 - __clz(wl));
    else {
        for (int k = wi - 1; k >= 0; --k) {
            const u32 mk = inv ? ~m[k] : m[k];
            if (mk) { dl = i - (k * 32 + 31 - __clz(mk)); break; }
        }
    }
    u32 wr = mw & himask;
    int dr = 100000;
    if (wr) dr = (__ffs(wr) - 1) - bi;
    else {
        for (int k = wi + 1; k < 8; ++k) {
            const u32 mk = inv ? ~m[k] : m[k];
            if (mk) { dr = (k * 32 + __ffs(mk) - 1) - i; break; }
        }
    }
    const int d = min(dl, dr);
    return (d >= 1000) ? 1e10f : (float)(d * d);
}

// ---------------------------------------------------------------------------
// 512-thread blocks: thread = (column x, row-group g). Block covers 8 output
// rows of one image; 16 decoded rows split 8 per group. Branchless bit decode
// (zero-padded word rows); both class distances packed u16x2; packed windowed
// min-plus (K=4); exactness check + exact float fallback; fused sigmoid +
// partials; last-block deterministic finalize.
// ---------------------------------------------------------------------------
__global__ __launch_bounds__(NTH) void fused(const float* __restrict__ pred,
                                             const float* __restrict__ target,
                                             const int* __restrict__ fl_ptr,
                                             float* __restrict__ out) {
    const int blk  = blockIdx.x;
    const int tid  = threadIdx.x;
    const int warp = tid >> 5;             // 0..15
    const int lane = tid & 31;
    const int x    = tid & 255;            // column
    const int g    = tid >> 8;             // row group 0/1

    const int b  = blk >> 5;               // image  (32 blocks per image)
    const int y0 = (blk & 31) * RR;        // first output row
    const int base = b * HH * WW;

    __shared__ u32 sbits[DR][10];          // zero-padded bit rows: [0]=[9]=0
    __shared__ union {
        u32 sd[DR][WW];                    // decoded packed pairs (fast path)
        u32 sfull[HH][8];                  // fallback: full-image bit rows
    } un;
    __shared__ float rs[16][4];
    __shared__ double fg[8][2];
    __shared__ int s_last;

    // ---- Hoisted global loads ----------------------------------------------
    const int fl = *fl_ptr;
    float pv[RPG];
#pragma unroll
    for (int il = 0; il < RPG; ++il)
        pv[il] = pred[base + (y0 + g * RPG + il) * WW + x];

    // zero the pad words
    if (tid < DR * 2) sbits[tid >> 1][(tid & 1) * 9] = 0u;

    // ---- ballots: warp w covers 32 cols of 8 rows of its group -------------
    {
        const int seg = warp & 7;          // which 32-column segment
#pragma unroll
        for (int j = 0; j < DPT; ++j) {
            const int dr = g * DPT + j;    // decoded row index
            const int ry = y0 - 4 + dr;    // absolute row
            float t = 0.0f;
            if ((unsigned)ry < (unsigned)HH)
                t = target[base + ry * WW + (seg << 5) + lane];
            const u32 bal = __ballot_sync(0xffffffffu, t > 0.5f);
            if (lane == 0) sbits[dr][1 + seg] = bal;
        }
    }
    __syncthreads();

    // ---- branchless decode: 8 rows per thread -> packed pairs in smem ------
    const int sh   = x - 5;
    const int wiw1 = (sh >> 5) + 1;        // arithmetic shift: x<5 -> 0
    const int shr  = sh & 31;
    u32 vm = 0x7FFu;
    if (x < 5)   vm &= (0x7FFu << (5 - x));
    if (x > 250) vm &= (0x7FFu >> (x - 250));
    const u32 rvm = __brev(vm) >> 21;

#pragma unroll
    for (int j = 0; j < DPT; ++j) {
        const int dr = g * DPT + j;
        const int ry = y0 - 4 + dr;
        const u32 lo = sbits[dr][wiw1];
        const u32 hi = sbits[dr][wiw1 + 1];
        const u32 win  = __funnelshift_r(lo, hi, shr) & 0x7FFu;  // OOB bits are 0
        const u32 rwin = __brev(win) >> 21;
        // nearest 1: left side = bits 0..5 (center at 5), right via reversal
        const int d1 = min(__clz(win  & 0x3Fu) - 26, __clz(rwin & 0x3Fu) - 26);
        // nearest 0: complement within valid bits
        const u32 w0 = win ^ vm;
        const u32 r0 = rwin ^ rvm;
        const int d0 = min(__clz(w0 & 0x3Fu) - 26, __clz(r0 & 0x3Fu) - 26);
        const u32 pair = (u32)(d1 * d1) | ((u32)(d0 * d0) << 16);
        un.sd[dr][x] = ((unsigned)ry < (unsigned)HH) ? pair : PAD_PAIR;
    }
    __syncthreads();

    // ---- packed windowed column min-plus (K=4), 4 outputs per thread -------
    u32 R[RPG + 8];
#pragma unroll
    for (int k = 0; k < RPG + 8; ++k) R[k] = un.sd[g * RPG + k][x];

    const u32 C1  = 0x00010001u * 1u;
    const u32 C4  = 0x00010001u * 4u;
    const u32 C9  = 0x00010001u * 9u;
    const u32 C16 = 0x00010001u * 16u;
    u32 mp[RPG];
#pragma unroll
    for (int il = 0; il < RPG; ++il) {
        u32 v = R[il + 4];
        v = __vminu2(v, __vminu2(R[il + 3] + C1,  R[il + 5] + C1));
        v = __vminu2(v, __vminu2(R[il + 2] + C4,  R[il + 6] + C4));
        v = __vminu2(v, __vminu2(R[il + 1] + C9,  R[il + 7] + C9));
        v = __vminu2(v, __vminu2(R[il]     + C16, R[il + 8] + C16));
        mp[il] = v;
    }

    // class bit per output (from ballot bits)
    int tb[RPG];
#pragma unroll
    for (int il = 0; il < RPG; ++il)
        tb[il] = (sbits[g * RPG + il + 4][1 + (x >> 5)] >> (x & 31)) & 1u;

    // ---- exactness check ----------------------------------------------------
    const u32 mx2 = __vmaxu2(__vmaxu2(mp[0], mp[1]), __vmaxu2(mp[2], mp[3]));
    const u32 mxv = max(mx2 & 0xFFFFu, mx2 >> 16);
    float msel[RPG];
    const int need_full = __syncthreads_or((int)(mxv > 25u));
    if (!need_full) {
#pragma unroll
        for (int il = 0; il < RPG; ++il)
            msel[il] = (float)(tb[il] ? (mp[il] >> 16) : (mp[il] & 0xFFFFu));
    } else {
        // Exact full-image float fallback (deterministic; ~never executes).
        for (int e = tid; e < HH * 8; e += NTH) ((u32*)un.sfull)[e] = 0u;
        __syncthreads();
        for (int it = 0; it < 16; ++it) {
            const int seg256 = warp + 16 * it;      // 0..255
            const int r  = seg256 >> 3;
            const int sg = seg256 & 7;
            const float t = target[base + r * WW + (sg << 5) + lane];
            const u32 bal = __ballot_sync(0xffffffffu, t > 0.5f);
            if (lane == 0) un.sfull[r][sg] = bal;
        }
        __syncthreads();
        float mf[RPG];
#pragma unroll
        for (int il = 0; il < RPG; ++il) mf[il] = 3.0e38f;
        for (int r = 0; r < HH; ++r) {
            const float d1 = exact_dist2(un.sfull[r], x, false);
            const float d0 = exact_dist2(un.sfull[r], x, true);
#pragma unroll
            for (int il = 0; il < RPG; ++il) {
                const int dy = y0 + g * RPG + il - r;
                const float dv = tb[il] ? d0 : d1;
                mf[il] = fminf(mf[il], dv + (float)(dy * dy));
            }
        }
#pragma unroll
        for (int il = 0; il < RPG; ++il) msel[il] = mf[il];
    }

    // ---- epilogue: sigmoid + partial sums ----------------------------------
    float s_pd = 0.0f, s_pt = 0.0f, s_pp = 0.0f;
    int s_tt = 0;
#pragma unroll
    for (int il = 0; il < RPG; ++il) {
        float p = pv[il];
        if (fl) p = __fdividef(1.0f, 1.0f + __expf(-p));
        s_pd += p * sqrtf(msel[il]);       // dist_map = dist to opposite class
        s_pp += p * p;
        if (tb[il]) { s_pt += p; s_tt += 1; }
    }
    float s_ttf = (float)s_tt;

#pragma unroll
    for (int off = 16; off > 0; off >>= 1) {
        s_pd  += __shfl_down_sync(0xffffffffu, s_pd,  off);
        s_pt  += __shfl_down_sync(0xffffffffu, s_pt,  off);
        s_pp  += __shfl_down_sync(0xffffffffu, s_pp,  off);
        s_ttf += __shfl_down_sync(0xffffffffu, s_ttf, off);
    }
    if (lane == 0) {
        rs[warp][0] = s_pd; rs[warp][1] = s_pt;
        rs[warp][2] = s_pp; rs[warp][3] = s_ttf;
    }
    __syncthreads();

    if (warp == 0) {
        float a0 = 0.f, a1 = 0.f, a2 = 0.f, a3 = 0.f;
        if (lane < 16) {
            a0 = rs[lane][0]; a1 = rs[lane][1];
            a2 = rs[lane][2]; a3 = rs[lane][3];
        }
#pragma unroll
        for (int off = 8; off > 0; off >>= 1) {
            a0 += __shfl_down_sync(0xffffffffu, a0, off);
            a1 += __shfl_down_sync(0xffffffffu, a1, off);
            a2 += __shfl_down_sync(0xffffffffu, a2, off);
            a3 += __shfl_down_sync(0xffffffffu, a3, off);
        }
        if (lane == 0) {
            d_partials[blk][0] = (double)a0; d_partials[blk][1] = (double)a1;
            d_partials[blk][2] = (double)a2; d_partials[blk][3] = (double)a3;
            __threadfence();
            const int old = atomicAdd(&g_fin, 1);
            s_last = (old == NBLK - 1);
        }
    }
    __syncthreads();
    if (!s_last) return;

    // ---- last block: deterministic finalize --------------------------------
    __threadfence();
    if (warp < 8) {
        const int img = warp;              // one warp per image (32 partials)
        const int s = img * 32 + lane;
        double v0 = d_partials[s][0];
        double v1 = d_partials[s][1];
        double v2 = d_partials[s][2];
        double v3 = d_partials[s][3];
#pragma unroll
        for (int off = 16; off > 0; off >>= 1) {
            v0 += __shfl_down_sync(0xffffffffu, v0, off);
            v1 += __shfl_down_sync(0xffffffffu, v1, off);
            v2 += __shfl_down_sync(0xffffffffu, v2, off);
            v3 += __shfl_down_sync(0xffffffffu, v3, off);
        }
        if (lane == 0) {
            const double eps = 1e-6;
            fg[img][0] = v0;                                      // boundary sum
            fg[img][1] = 1.0 - (2.0 * v1 + eps) / (v2 + v3 + eps); // dice term
        }
    }
    __syncthreads();
    if (tid == 0) {
        double bl = 0.0, dl = 0.0;
#pragma unroll
        for (int i = 0; i < BB; ++i) { bl += fg[i][0]; dl += fg[i][1]; }
        dl /= (double)BB;
        bl /= (double)(BB * HH * WW);
        out[0] = (float)(dl + bl);  // ALPHA = BETA = 1
        g_fin = 0;                  // reset for next (graph) replay
        __threadfence();
    }
}

// ---------------------------------------------------------------------------
extern "C" void kernel_launch(void* const* d_in, const int* in_sizes, int n_in,
                              void* d_out, int out_size) {
    const float* pred   = (const float*)d_in[0];
    const float* target = (const float*)d_in[1];
    const int*   fl     = (const int*)d_in[2];
    float* out = (float*)d_out;

    fused<<<NBLK, NTH>>>(pred, target, fl, out);
}

// round 12
// speedup vs baseline: 1.5496x; 1.0129x over previous
#include <cuda_runtime.h>
#include <math.h>

// Problem constants (match reference)
#define BB 8
#define HH 256
#define WW 256
#define RR 8                        // output rows per block
#define NG 2                        // row groups (thread split)
#define RPG (RR / NG)               // output rows per thread (4)
#define DR 16                       // decoded rows per block (RR + 2*4)
#define DPT (DR / NG)               // ballot rows per warp-set (8)
#define NBLK (BB * (HH / RR))       // 256 blocks
#define NTH  (WW * NG)              // 512 threads
#define PAD_PAIR 0x00240024u        // (36,36): >25 -> can only force fallback

typedef unsigned u32;
typedef unsigned short u16;

// ---------------------------------------------------------------------------
// Scratch (device globals — no allocation allowed)
// ---------------------------------------------------------------------------
__device__ double d_partials[NBLK][4];   // {sum p*dist, sum p*t, sum p*p, sum t*t}
__device__ int g_fin;                    // finalize election counter (self-resetting)

// Exact squared distance to nearest set (inv=false) / clear (inv=true) bit in
// a 256-bit row mask (1e10 if none == reference INF). Fallback-only.
__device__ __forceinline__ float exact_dist2(const u32* m, int i, bool inv) {
    const int wi = i >> 5, bi = i & 31;
    const u32 mw = inv ? ~m[wi] : m[wi];
    const u32 lowmask = (2u << bi) - 1u;
    const u32 himask  = ~((1u << bi) - 1u);
    u32 wl = mw & lowmask;
    int dl = 100000;
    if (wl) dl = bi - (31 - __clz(wl));
    else {
        for (int k = wi - 1; k >= 0; --k) {
            const u32 mk = inv ? ~m[k] : m[k];
            if (mk) { dl = i - (k * 32 + 31 - __clz(mk)); break; }
        }
    }
    u32 wr = mw & himask;
    int dr = 100000;
    if (wr) dr = (__ffs(wr) - 1) - bi;
    else {
        for (int k = wi + 1; k < 8; ++k) {
            const u32 mk = inv ? ~m[k] : m[k];
            if (mk) { dr = (k * 32 + __ffs(mk) - 1) - i; break; }
        }
    }
    const int d = min(dl, dr);
    return (d >= 1000) ? 1e10f : (float)(d * d);
}

// Distance (0..6) from center (bit 5) to nearest set bit of an 11-bit mask.
__device__ __forceinline__ int win_dist(u32 m) {
    const u32 r = __brev(m) >> 21;             // 11-bit reversal
    const int dl = __clz(m & 0x3Fu) - 26;      // left side incl. center
    const int dr = __clz(r & 0x3Fu) - 26;      // right side incl. center
    return min(dl, dr);                        // 6 if empty
}

// ---------------------------------------------------------------------------
// 512-thread blocks: thread = (column x, row-group g). Block = 8 output rows
// of one image. Shared 2048-entry LUT: 11-bit window -> dist^2 (u16).
// Ballot bit rows -> register-direct LUT decode (12 rows/thread, packed
// u16x2 pairs) -> packed windowed min-plus (K=4) -> exactness check + exact
// fallback -> fused sigmoid + partials -> last-block finalize.
// ---------------------------------------------------------------------------
__global__ __launch_bounds__(NTH) void fused(const float* __restrict__ pred,
                                             const float* __restrict__ target,
                                             const int* __restrict__ fl_ptr,
                                             float* __restrict__ out) {
    const int blk  = blockIdx.x;
    const int tid  = threadIdx.x;
    const int warp = tid >> 5;             // 0..15
    const int lane = tid & 31;
    const int x    = tid & 255;            // column
    const int g    = tid >> 8;             // row group 0/1

    const int b  = blk >> 5;               // image  (32 blocks per image)
    const int y0 = (blk & 31) * RR;        // first output row
    const int base = b * HH * WW;

    __shared__ u32 sbits[DR][10];          // zero-padded bit rows: [0]=[9]=0
    __shared__ union {
        u16 lut[2048];                     // fast path: window -> dist^2
        u32 sfull[HH][8];                  // fallback: full-image bit rows
    } un;
    __shared__ float rs[16][4];
    __shared__ double fg[8][2];
    __shared__ int s_last;

    // ---- Hoisted global loads ----------------------------------------------
    const int fl = *fl_ptr;
    float pv[RPG];
#pragma unroll
    for (int il = 0; il < RPG; ++il)
        pv[il] = pred[base + (y0 + g * RPG + il) * WW + x];

    // zero the pad words
    if (tid < DR * 2) sbits[tid >> 1][(tid & 1) * 9] = 0u;

    // ---- build the distance LUT (4 entries/thread) -------------------------
#pragma unroll
    for (int e = 0; e < 4; ++e) {
        const u32 m = tid + e * NTH;
        const int d = win_dist(m);
        un.lut[m] = (u16)(d * d);
    }

    // ---- ballots: warp covers 32 cols x 8 rows of its group ----------------
    {
        const int seg = warp & 7;          // 32-column segment
#pragma unroll
        for (int j = 0; j < DPT; ++j) {
            const int dr = (warp >> 3) * DPT + j;   // decoded row index
            const int ry = y0 - 4 + dr;             // absolute row
            float t = 0.0f;
            if ((unsigned)ry < (unsigned)HH)
                t = target[base + ry * WW + (seg << 5) + lane];
            const u32 bal = __ballot_sync(0xffffffffu, t > 0.5f);
            if (lane == 0) sbits[dr][1 + seg] = bal;
        }
    }
    __syncthreads();

    // ---- register-direct LUT decode: 12 rows per thread --------------------
    const int sh   = x - 5;
    const int wiw1 = (sh >> 5) + 1;        // arithmetic shift: x<5 -> 0 (pad)
    const int shr  = sh & 31;
    u32 vm = 0x7FFu;
    if (x < 5)   vm &= (0x7FFu << (5 - x));
    if (x > 250) vm &= (0x7FFu >> (x - 250));

    u32 R[RPG + 8];
#pragma unroll
    for (int k = 0; k < RPG + 8; ++k) {
        const int dr = g * RPG + k;
        const int ry = y0 - 4 + dr;
        const u32 lo = sbits[dr][wiw1];
        const u32 hi = sbits[dr][wiw1 + 1];
        const u32 win = __funnelshift_r(lo, hi, shr) & 0x7FFu;  // OOB bits 0
        const u32 d1q = (u32)un.lut[win];
        const u32 d0q = (u32)un.lut[(win ^ 0x7FFu) & vm];
        const u32 pair = d1q | (d0q << 16);
        R[k] = ((unsigned)ry < (unsigned)HH) ? pair : PAD_PAIR;
    }

    // ---- packed windowed column min-plus (K=4), 4 outputs per thread -------
    const u32 C1  = 0x00010001u * 1u;
    const u32 C4  = 0x00010001u * 4u;
    const u32 C9  = 0x00010001u * 9u;
    const u32 C16 = 0x00010001u * 16u;
    u32 mp[RPG];
#pragma unroll
    for (int il = 0; il < RPG; ++il) {
        u32 v = R[il + 4];
        v = __vminu2(v, __vminu2(R[il + 3] + C1,  R[il + 5] + C1));
        v = __vminu2(v, __vminu2(R[il + 2] + C4,  R[il + 6] + C4));
        v = __vminu2(v, __vminu2(R[il + 1] + C9,  R[il + 7] + C9));
        v = __vminu2(v, __vminu2(R[il]     + C16, R[il + 8] + C16));
        mp[il] = v;
    }

    // class bit per output (from ballot bits)
    int tb[RPG];
#pragma unroll
    for (int il = 0; il < RPG; ++il)
        tb[il] = (sbits[g * RPG + il + 4][1 + (x >> 5)] >> (x & 31)) & 1u;

    // ---- exactness check ----------------------------------------------------
    const u32 mx2 = __vmaxu2(__vmaxu2(mp[0], mp[1]), __vmaxu2(mp[2], mp[3]));
    const u32 mxv = max(mx2 & 0xFFFFu, mx2 >> 16);
    float msel[RPG];
    const int need_full = __syncthreads_or((int)(mxv > 25u));
    if (!need_full) {
#pragma unroll
        for (int il = 0; il < RPG; ++il)
            msel[il] = (float)(tb[il] ? (mp[il] >> 16) : (mp[il] & 0xFFFFu));
    } else {
        // Exact full-image float fallback (deterministic; ~never executes).
        for (int it = 0; it < (HH * 8) / 16; ++it) {   // 2048 warp-tasks / 16 warps
            const int task = warp + 16 * it;
            const int r  = task >> 3;
            const int sg = task & 7;
            const float t = target[base + r * WW + (sg << 5) + lane];
            const u32 bal = __ballot_sync(0xffffffffu, t > 0.5f);
            if (lane == 0) un.sfull[r][sg] = bal;
        }
        __syncthreads();
        float mf[RPG];
#pragma unroll
        for (int il = 0; il < RPG; ++il) mf[il] = 3.0e38f;
        for (int r = 0; r < HH; ++r) {
            const float d1 = exact_dist2(un.sfull[r], x, false);
            const float d0 = exact_dist2(un.sfull[r], x, true);
#pragma unroll
            for (int il = 0; il < RPG; ++il) {
                const int dy = y0 + g * RPG + il - r;
                const float dv = tb[il] ? d0 : d1;
                mf[il] = fminf(mf[il], dv + (float)(dy * dy));
            }
        }
#pragma unroll
        for (int il = 0; il < RPG; ++il) msel[il] = mf[il];
    }

    // ---- epilogue: sigmoid + partial sums ----------------------------------
    float s_pd = 0.0f, s_pt = 0.0f, s_pp = 0.0f;
    int s_tt = 0;
#pragma unroll
    for (int il = 0; il < RPG; ++il) {
        float p = pv[il];
        if (fl) p = __fdividef(1.0f, 1.0f + __expf(-p));
        s_pd += p * sqrtf(msel[il]);       // dist_map = dist to opposite class
        s_pp += p * p;
        if (tb[il]) { s_pt += p; s_tt += 1; }
    }
    float s_ttf = (float)s_tt;

#pragma unroll
    for (int off = 16; off > 0; off >>= 1) {
        s_pd  += __shfl_down_sync(0xffffffffu, s_pd,  off);
        s_pt  += __shfl_down_sync(0xffffffffu, s_pt,  off);
        s_pp  += __shfl_down_sync(0xffffffffu, s_pp,  off);
        s_ttf += __shfl_down_sync(0xffffffffu, s_ttf, off);
    }
    if (lane == 0) {
        rs[warp][0] = s_pd; rs[warp][1] = s_pt;
        rs[warp][2] = s_pp; rs[warp][3] = s_ttf;
    }
    __syncthreads();

    if (warp == 0) {
        float a0 = 0.f, a1 = 0.f, a2 = 0.f, a3 = 0.f;
        if (lane < 16) {
            a0 = rs[lane][0]; a1 = rs[lane][1];
            a2 = rs[lane][2]; a3 = rs[lane][3];
        }
#pragma unroll
        for (int off = 8; off > 0; off >>= 1) {
            a0 += __shfl_down_sync(0xffffffffu, a0, off);
            a1 += __shfl_down_sync(0xffffffffu, a1, off);
            a2 += __shfl_down_sync(0xffffffffu, a2, off);
            a3 += __shfl_down_sync(0xffffffffu, a3, off);
        }
        if (lane == 0) {
            d_partials[blk][0] = (double)a0; d_partials[blk][1] = (double)a1;
            d_partials[blk][2] = (double)a2; d_partials[blk][3] = (double)a3;
            __threadfence();
            const int old = atomicAdd(&g_fin, 1);
            s_last = (old == NBLK - 1);
        }
    }
    __syncthreads();
    if (!s_last) return;

    // ---- last block: deterministic finalize --------------------------------
    __threadfence();
    if (warp < 8) {
        const int img = warp;              // one warp per image (32 partials)
        const int s = img * 32 + lane;
        double v0 = d_partials[s][0];
        double v1 = d_partials[s][1];
        double v2 = d_partials[s][2];
        double v3 = d_partials[s][3];
#pragma unroll
        for (int off = 16; off > 0; off >>= 1) {
            v0 += __shfl_down_sync(0xffffffffu, v0, off);
            v1 += __shfl_down_sync(0xffffffffu, v1, off);
            v2 += __shfl_down_sync(0xffffffffu, v2, off);
            v3 += __shfl_down_sync(0xffffffffu, v3, off);
        }
        if (lane == 0) {
            const double eps = 1e-6;
            fg[img][0] = v0;                                       // boundary sum
            fg[img][1] = 1.0 - (2.0 * v1 + eps) / (v2 + v3 + eps); // dice term
        }
    }
    __syncthreads();
    if (tid == 0) {
        double bl = 0.0, dl = 0.0;
#pragma unroll
        for (int i = 0; i < BB; ++i) { bl += fg[i][0]; dl += fg[i][1]; }
        dl /= (double)BB;
        bl /= (double)(BB * HH * WW);
        out[0] = (float)(dl + bl);  // ALPHA = BETA = 1
        g_fin = 0;                  // reset for next (graph) replay
        __threadfence();
    }
}

// ---------------------------------------------------------------------------
extern "C" void kernel_launch(void* const* d_in, const int* in_sizes, int n_in,
                              void* d_out, int out_size) {
    const float* pred   = (const float*)d_in[0];
    const float* target = (const float*)d_in[1];
    const int*   fl     = (const int*)d_in[2];
    float* out = (float*)d_out;

    fused<<<NBLK, NTH>>>(pred, target, fl, out);
}

// round 13
// speedup vs baseline: 1.6605x; 1.0716x over previous
#include <cuda_runtime.h>
#include <math.h>

// Problem constants (match reference)
#define BB 8
#define HH 256
#define WW 256
#define RR 8                        // output rows per block
#define NG 2                        // row groups (thread split)
#define RPG (RR / NG)               // output rows per thread (4)
#define KW 2                        // column window radius (exactness-checked)
#define DR (RR + 2 * KW)            // decoded rows per block (12)
#define NBLK (BB * (HH / RR))       // 256 blocks
#define NTH  (WW * NG)              // 512 threads
#define PAD_PAIR 0x00100010u        // (16,16): >9 -> can only force fallback

typedef unsigned u32;

// ---------------------------------------------------------------------------
// Scratch (device globals — no allocation allowed)
// ---------------------------------------------------------------------------
__device__ double d_partials[NBLK][4];   // {sum p*dist, sum p*t, sum p*p, sum t*t}
__device__ int g_fin;                    // finalize election counter (self-resetting)

// Exact squared distance to nearest set (inv=false) / clear (inv=true) bit in
// a 256-bit row mask (1e10 if none == reference INF). Fallback-only.
__device__ __forceinline__ float exact_dist2(const u32* m, int i, bool inv) {
    const int wi = i >> 5, bi = i & 31;
    const u32 mw = inv ? ~m[wi] : m[wi];
    const u32 lowmask = (2u << bi) - 1u;
    const u32 himask  = ~((1u << bi) - 1u);
    u32 wl = mw & lowmask;
    int dl = 100000;
    if (wl) dl = bi - (31 - __clz(wl));
    else {
        for (int k = wi - 1; k >= 0; --k) {
            const u32 mk = inv ? ~m[k] : m[k];
            if (mk) { dl = i - (k * 32 + 31 - __clz(mk)); break; }
        }
    }
    u32 wr = mw & himask;
    int dr = 100000;
    if (wr) dr = (__ffs(wr) - 1) - bi;
    else {
        for (int k = wi + 1; k < 8; ++k) {
            const u32 mk = inv ? ~m[k] : m[k];
            if (mk) { dr = (k * 32 + __ffs(mk) - 1) - i; break; }
        }
    }
    const int d = min(dl, dr);
    return (d >= 1000) ? 1e10f : (float)(d * d);
}

// ---------------------------------------------------------------------------
// 512-thread blocks: thread = (column x, row-group g). Block = 8 output rows
// of one image. K=2 window: 7-bit row windows, row-dist clamp 4, packed u16x2
// pairs, 5-tap packed min-plus, exact iff result <= 9 else exact fallback.
// ---------------------------------------------------------------------------
__global__ __launch_bounds__(NTH) void fused(const float* __restrict__ pred,
                                             const float* __restrict__ target,
                                             const int* __restrict__ fl_ptr,
                                             float* __restrict__ out) {
    const int blk  = blockIdx.x;
    const int tid  = threadIdx.x;
    const int warp = tid >> 5;             // 0..15
    const int lane = tid & 31;
    const int x    = tid & 255;            // column
    const int g    = tid >> 8;             // row group 0/1

    const int b  = blk >> 5;               // image  (32 blocks per image)
    const int y0 = (blk & 31) * RR;        // first output row
    const int base = b * HH * WW;

    __shared__ u32 sbits[DR][10];          // zero-padded bit rows: [0]=[9]=0
    __shared__ u32 sfull[HH][8];           // fallback-only: full-image bit rows
    __shared__ float rs[16][4];
    __shared__ double fg[8][2];
    __shared__ int s_last;

    // ---- Hoisted global loads ----------------------------------------------
    const int fl = *fl_ptr;
    float pv[RPG];
#pragma unroll
    for (int il = 0; il < RPG; ++il)
        pv[il] = pred[base + (y0 + g * RPG + il) * WW + x];

    // zero the pad words
    if (tid < DR * 2) sbits[tid >> 1][(tid & 1) * 9] = 0u;

    // ---- ballots: 96 warp-tasks (12 rows x 8 segments) over 16 warps -------
#pragma unroll
    for (int it = 0; it < 6; ++it) {
        const int task = warp + 16 * it;   // 0..95
        const int dr  = task >> 3;
        const int seg = task & 7;
        const int ry  = y0 - KW + dr;
        float t = 0.0f;
        if ((unsigned)ry < (unsigned)HH)
            t = target[base + ry * WW + (seg << 5) + lane];
        const u32 bal = __ballot_sync(0xffffffffu, t > 0.5f);
        if (lane == 0) sbits[dr][1 + seg] = bal;
    }
    __syncthreads();

    // ---- register decode: 8 rows/thread, 7-bit windows, clamp 4 ------------
    const int sh   = x - 3;
    const int wiw1 = (sh >> 5) + 1;        // arithmetic shift: x<3 -> 0 (pad)
    const int shr  = sh & 31;
    u32 vm = 0x7Fu;
    if (x < 3)   vm &= (0x7Fu << (3 - x));
    if (x > 252) vm &= (0x7Fu >> (x - 252));

    u32 R[RPG + 2 * KW];
#pragma unroll
    for (int k = 0; k < RPG + 2 * KW; ++k) {
        const int dr = g * RPG + k;
        const int ry = y0 - KW + dr;
        const u32 lo = sbits[dr][wiw1];
        const u32 hi = sbits[dr][wiw1 + 1];
        const u32 win = __funnelshift_r(lo, hi, shr) & 0x7Fu;   // OOB bits 0
        // nearest 1 (center bit 3)
        u32 rv = __brev(win) >> 25;                             // 7-bit reversal
        const int d1 = min(__clz(win & 0xFu) - 28, __clz(rv & 0xFu) - 28);
        // nearest 0 (complement within valid bits)
        const u32 w0 = (win ^ 0x7Fu) & vm;
        rv = __brev(w0) >> 25;
        const int d0 = min(__clz(w0 & 0xFu) - 28, __clz(rv & 0xFu) - 28);
        const u32 pair = (u32)(d1 * d1) | ((u32)(d0 * d0) << 16);
        R[k] = ((unsigned)ry < (unsigned)HH) ? pair : PAD_PAIR;
    }

    // ---- packed windowed column min-plus (K=2), 4 outputs per thread -------
    const u32 C1 = 0x00010001u;
    const u32 C4 = 0x00040004u;
    u32 mp[RPG];
#pragma unroll
    for (int il = 0; il < RPG; ++il) {
        u32 v = R[il + 2];
        v = __vminu2(v, __vminu2(R[il + 1], R[il + 3]) + C1);
        v = __vminu2(v, __vminu2(R[il],     R[il + 4]) + C4);
        mp[il] = v;
    }

    // class bit per output (from ballot bits)
    int tb[RPG];
#pragma unroll
    for (int il = 0; il < RPG; ++il)
        tb[il] = (sbits[g * RPG + il + KW][1 + (x >> 5)] >> (x & 31)) & 1u;

    // ---- exactness check: valid iff every windowed min <= 9 ----------------
    const u32 mx2 = __vmaxu2(__vmaxu2(mp[0], mp[1]), __vmaxu2(mp[2], mp[3]));
    const u32 mxv = max(mx2 & 0xFFFFu, mx2 >> 16);
    float msel[RPG];
    const int need_full = __syncthreads_or((int)(mxv > 9u));
    if (!need_full) {
#pragma unroll
        for (int il = 0; il < RPG; ++il)
            msel[il] = (float)(tb[il] ? (mp[il] >> 16) : (mp[il] & 0xFFFFu));
    } else {
        // Exact full-image float fallback (deterministic; rarely executes).
        for (int it = 0; it < (HH * 8) / 16; ++it) {   // 2048 warp-tasks
            const int task = warp + 16 * it;
            const int r  = task >> 3;
            const int sg = task & 7;
            const float t = target[base + r * WW + (sg << 5) + lane];
            const u32 bal = __ballot_sync(0xffffffffu, t > 0.5f);
            if (lane == 0) sfull[r][sg] = bal;
        }
        __syncthreads();
        float mf[RPG];
#pragma unroll
        for (int il = 0; il < RPG; ++il) mf[il] = 3.0e38f;
        for (int r = 0; r < HH; ++r) {
            const float d1 = exact_dist2(sfull[r], x, false);
            const float d0 = exact_dist2(sfull[r], x, true);
#pragma unroll
            for (int il = 0; il < RPG; ++il) {
                const int dy = y0 + g * RPG + il - r;
                const float dv = tb[il] ? d0 : d1;
                mf[il] = fminf(mf[il], dv + (float)(dy * dy));
            }
        }
#pragma unroll
        for (int il = 0; il < RPG; ++il) msel[il] = mf[il];
    }

    // ---- epilogue: sigmoid + partial sums ----------------------------------
    float s_pd = 0.0f, s_pt = 0.0f, s_pp = 0.0f;
    int s_tt = 0;
#pragma unroll
    for (int il = 0; il < RPG; ++il) {
        float p = pv[il];
        if (fl) p = __fdividef(1.0f, 1.0f + __expf(-p));
        s_pd += p * sqrtf(msel[il]);       // dist_map = dist to opposite class
        s_pp += p * p;
        if (tb[il]) { s_pt += p; s_tt += 1; }
    }
    float s_ttf = (float)s_tt;

#pragma unroll
    for (int off = 16; off > 0; off >>= 1) {
        s_pd  += __shfl_down_sync(0xffffffffu, s_pd,  off);
        s_pt  += __shfl_down_sync(0xffffffffu, s_pt,  off);
        s_pp  += __shfl_down_sync(0xffffffffu, s_pp,  off);
        s_ttf += __shfl_down_sync(0xffffffffu, s_ttf, off);
    }
    if (lane == 0) {
        rs[warp][0] = s_pd; rs[warp][1] = s_pt;
        rs[warp][2] = s_pp; rs[warp][3] = s_ttf;
    }
    __syncthreads();

    if (warp == 0) {
        float a0 = 0.f, a1 = 0.f, a2 = 0.f, a3 = 0.f;
        if (lane < 16) {
            a0 = rs[lane][0]; a1 = rs[lane][1];
            a2 = rs[lane][2]; a3 = rs[lane][3];
        }
#pragma unroll
        for (int off = 8; off > 0; off >>= 1) {
            a0 += __shfl_down_sync(0xffffffffu, a0, off);
            a1 += __shfl_down_sync(0xffffffffu, a1, off);
            a2 += __shfl_down_sync(0xffffffffu, a2, off);
            a3 += __shfl_down_sync(0xffffffffu, a3, off);
        }
        if (lane == 0) {
            d_partials[blk][0] = (double)a0; d_partials[blk][1] = (double)a1;
            d_partials[blk][2] = (double)a2; d_partials[blk][3] = (double)a3;
            __threadfence();
            const int old = atomicAdd(&g_fin, 1);
            s_last = (old == NBLK - 1);
        }
    }
    __syncthreads();
    if (!s_last) return;

    // ---- last block: deterministic finalize --------------------------------
    __threadfence();
    if (warp < 8) {
        const int img = warp;              // one warp per image (32 partials)
        const int s = img * 32 + lane;
        double v0 = d_partials[s][0];
        double v1 = d_partials[s][1];
        double v2 = d_partials[s][2];
        double v3 = d_partials[s][3];
#pragma unroll
        for (int off = 16; off > 0; off >>= 1) {
            v0 += __shfl_down_sync(0xffffffffu, v0, off);
            v1 += __shfl_down_sync(0xffffffffu, v1, off);
            v2 += __shfl_down_sync(0xffffffffu, v2, off);
            v3 += __shfl_down_sync(0xffffffffu, v3, off);
        }
        if (lane == 0) {
            const double eps = 1e-6;
            fg[img][0] = v0;                                       // boundary sum
            fg[img][1] = 1.0 - (2.0 * v1 + eps) / (v2 + v3 + eps); // dice term
        }
    }
    __syncthreads();
    if (tid == 0) {
        double bl = 0.0, dl = 0.0;
#pragma unroll
        for (int i = 0; i < BB; ++i) { bl += fg[i][0]; dl += fg[i][1]; }
        dl /= (double)BB;
        bl /= (double)(BB * HH * WW);
        out[0] = (float)(dl + bl);  // ALPHA = BETA = 1
        g_fin = 0;                  // reset for next (graph) replay
        __threadfence();
    }
}

// ---------------------------------------------------------------------------
extern "C" void kernel_launch(void* const* d_in, const int* in_sizes, int n_in,
                              void* d_out, int out_size) {
    const float* pred   = (const float*)d_in[0];
    const float* target = (const float*)d_in[1];
    const int*   fl     = (const int*)d_in[2];
    float* out = (float*)d_out;

    fused<<<NBLK, NTH>>>(pred, target, fl, out);
}

// round 14
// speedup vs baseline: 1.6721x; 1.0070x over previous
#include <cuda_runtime.h>
#include <math.h>

// Problem constants (match reference)
#define BB 8
#define HH 256
#define WW 256
#define RR 8                        // output rows per block
#define NG 2                        // row groups (thread split)
#define RPG (RR / NG)               // output rows per thread (4)
#define KW 2                        // column window radius (exactness-checked)
#define DR (RR + 2 * KW)            // decoded rows per block (12)
#define DPT (DR / NG)               // decoded rows per thread (6)
#define NBLK (BB * (HH / RR))       // 256 blocks
#define NTH  (WW * NG)              // 512 threads
#define PAD_PAIR 0x00100010u        // (16,16): >9 -> can only force fallback

typedef unsigned u32;

// ---------------------------------------------------------------------------
// Scratch (device globals — no allocation allowed)
// ---------------------------------------------------------------------------
__device__ double d_partials[NBLK][4];   // {sum p*dist, sum p*t, sum p*p, sum t}
__device__ int g_fin;                    // finalize election counter (self-resetting)

// Exact squared distance to nearest set (inv=false) / clear (inv=true) bit in
// a 256-bit row mask (1e10 if none == reference INF). Fallback-only.
__device__ __forceinline__ float exact_dist2(const u32* m, int i, bool inv) {
    const int wi = i >> 5, bi = i & 31;
    const u32 mw = inv ? ~m[wi] : m[wi];
    const u32 lowmask = (2u << bi) - 1u;
    const u32 himask  = ~((1u << bi) - 1u);
    u32 wl = mw & lowmask;
    int dl = 100000;
    if (wl) dl = bi - (31 - __clz(wl));
    else {
        for (int k = wi - 1; k >= 0; --k) {
            const u32 mk = inv ? ~m[k] : m[k];
            if (mk) { dl = i - (k * 32 + 31 - __clz(mk)); break; }
        }
    }
    u32 wr = mw & himask;
    int dr = 100000;
    if (wr) dr = (__ffs(wr) - 1) - bi;
    else {
        for (int k = wi + 1; k < 8; ++k) {
            const u32 mk = inv ? ~m[k] : m[k];
            if (mk) { dr = (k * 32 + __ffs(mk) - 1) - i; break; }
        }
    }
    const int d = min(dl, dr);
    return (d >= 1000) ? 1e10f : (float)(d * d);
}

// ---------------------------------------------------------------------------
// 512-thread blocks: thread = (column x, row-group g). Block = 8 output rows
// of one image. K=2 window. Shared decode: each group decodes 6 distinct rows
// into a pair tile; min-plus reads 8 rows from it. t-count via popc.
// ---------------------------------------------------------------------------
__global__ __launch_bounds__(NTH) void fused(const float* __restrict__ pred,
                                             const float* __restrict__ target,
                                             const int* __restrict__ fl_ptr,
                                             float* __restrict__ out) {
    const int blk  = blockIdx.x;
    const int tid  = threadIdx.x;
    const int warp = tid >> 5;             // 0..15
    const int lane = tid & 31;
    const int x    = tid & 255;            // column
    const int g    = tid >> 8;             // row group 0/1

    const int b  = blk >> 5;               // image  (32 blocks per image)
    const int y0 = (blk & 31) * RR;        // first output row
    const int base = b * HH * WW;

    __shared__ u32 sbits[DR][10];          // zero-padded bit rows: [0]=[9]=0
    __shared__ union {
        u32 sp[DR][WW];                    // fast path: decoded packed pairs
        u32 sfull[HH][8];                  // fallback: full-image bit rows
    } un;
    __shared__ float rs[16][3];
    __shared__ double fg[8][2];
    __shared__ int s_last;

    // ---- Hoisted global loads ----------------------------------------------
    const int fl = *fl_ptr;
    float pv[RPG];
#pragma unroll
    for (int il = 0; il < RPG; ++il)
        pv[il] = pred[base + (y0 + g * RPG + il) * WW + x];

    // zero the pad words
    if (tid < DR * 2) sbits[tid >> 1][(tid & 1) * 9] = 0u;

    // ---- ballots: 96 warp-tasks (12 rows x 8 segments), clamped loads ------
#pragma unroll
    for (int it = 0; it < 6; ++it) {
        const int task = warp + 16 * it;   // 0..95
        const int dr  = task >> 3;
        const int seg = task & 7;
        const int ry  = min(max(y0 - KW + dr, 0), HH - 1);   // clamped
        const float t = target[base + ry * WW + (seg << 5) + lane];
        const u32 bal = __ballot_sync(0xffffffffu, t > 0.5f);
        if (lane == 0) sbits[dr][1 + seg] = bal;
    }
    __syncthreads();

    // ---- decode 6 distinct rows per thread into the pair tile --------------
    const int sh   = x - 3;
    const int wiw1 = (sh >> 5) + 1;        // arithmetic shift: x<3 -> 0 (pad)
    const int shr  = sh & 31;
    u32 vm = 0x7Fu;
    if (x < 3)   vm &= (0x7Fu << (3 - x));
    if (x > 252) vm &= (0x7Fu >> (x - 252));

#pragma unroll
    for (int j = 0; j < DPT; ++j) {
        const int dr = g * DPT + j;
        const int ry = y0 - KW + dr;
        const u32 lo = sbits[dr][wiw1];
        const u32 hi = sbits[dr][wiw1 + 1];
        const u32 win = __funnelshift_r(lo, hi, shr) & 0x7Fu;   // OOB bits 0
        // nearest 1 (center bit 3); pad zeros are harmless for class-1
        u32 rv = __brev(win) >> 25;                             // 7-bit reversal
        const int d1 = min(__clz(win & 0xFu) - 28, __clz(rv & 0xFu) - 28);
        // nearest 0: complement masked to valid bits
        const u32 w0 = (win ^ 0x7Fu) & vm;
        rv = __brev(w0) >> 25;
        const int d0 = min(__clz(w0 & 0xFu) - 28, __clz(rv & 0xFu) - 28);
        const u32 q1 = __byte_perm(0x09040100u, 0x10u, d1);     // d1^2
        const u32 q0 = __byte_perm(0x09040100u, 0x10u, d0);     // d0^2
        const u32 pair = q1 | (q0 << 16);
        un.sp[dr][x] = ((unsigned)ry < (unsigned)HH) ? pair : PAD_PAIR;
    }
    __syncthreads();

    // ---- read 8 rows, packed windowed min-plus (K=2) -----------------------
    u32 R[RPG + 2 * KW];
#pragma unroll
    for (int k = 0; k < RPG + 2 * KW; ++k) R[k] = un.sp[g * RPG + k][x];

    const u32 C1 = 0x00010001u;
    const u32 C4 = 0x00040004u;
    u32 mp[RPG];
#pragma unroll
    for (int il = 0; il < RPG; ++il) {
        u32 v = R[il + 2];
        v = __vminu2(v, __vminu2(R[il + 1], R[il + 3]) + C1);
        v = __vminu2(v, __vminu2(R[il],     R[il + 4]) + C4);
        mp[il] = v;
    }

    // class bit per output (from ballot bits)
    int tb[RPG];
#pragma unroll
    for (int il = 0; il < RPG; ++il)
        tb[il] = (sbits[g * RPG + il + KW][1 + (x >> 5)] >> (x & 31)) & 1u;

    // ---- exactness check: valid iff every windowed min <= 9 ----------------
    const u32 mx2 = __vmaxu2(__vmaxu2(mp[0], mp[1]), __vmaxu2(mp[2], mp[3]));
    const u32 mxv = max(mx2 & 0xFFFFu, mx2 >> 16);
    float msel[RPG];
    const int need_full = __syncthreads_or((int)(mxv > 9u));
    if (!need_full) {
#pragma unroll
        for (int il = 0; il < RPG; ++il)
            msel[il] = (float)(tb[il] ? (mp[il] >> 16) : (mp[il] & 0xFFFFu));
    } else {
        // Exact full-image float fallback (deterministic; rarely executes).
        for (int it = 0; it < (HH * 8) / 16; ++it) {   // 2048 warp-tasks
            const int task = warp + 16 * it;
            const int r  = task >> 3;
            const int sg = task & 7;
            const float t = target[base + r * WW + (sg << 5) + lane];
            const u32 bal = __ballot_sync(0xffffffffu, t > 0.5f);
            if (lane == 0) un.sfull[r][sg] = bal;
        }
        __syncthreads();
        float mf[RPG];
#pragma unroll
        for (int il = 0; il < RPG; ++il) mf[il] = 3.0e38f;
        for (int r = 0; r < HH; ++r) {
            const float d1 = exact_dist2(un.sfull[r], x, false);
            const float d0 = exact_dist2(un.sfull[r], x, true);
#pragma unroll
            for (int il = 0; il < RPG; ++il) {
                const int dy = y0 + g * RPG + il - r;
                const float dv = tb[il] ? d0 : d1;
                mf[il] = fminf(mf[il], dv + (float)(dy * dy));
            }
        }
#pragma unroll
        for (int il = 0; il < RPG; ++il) msel[il] = mf[il];
    }

    // ---- epilogue: sigmoid + partial sums (t-count via popc later) ---------
    float s_pd = 0.0f, s_pt = 0.0f, s_pp = 0.0f;
#pragma unroll
    for (int il = 0; il < RPG; ++il) {
        float p = pv[il];
        if (fl) p = __fdividef(1.0f, 1.0f + __expf(-p));
        s_pd += p * sqrtf(msel[il]);       // dist_map = dist to opposite class
        s_pp += p * p;
        if (tb[il]) s_pt += p;
    }

#pragma unroll
    for (int off = 16; off > 0; off >>= 1) {
        s_pd += __shfl_down_sync(0xffffffffu, s_pd, off);
        s_pt += __shfl_down_sync(0xffffffffu, s_pt, off);
        s_pp += __shfl_down_sync(0xffffffffu, s_pp, off);
    }
    if (lane == 0) {
        rs[warp][0] = s_pd; rs[warp][1] = s_pt; rs[warp][2] = s_pp;
    }
    __syncthreads();

    if (warp == 0) {
        float a0 = 0.f, a1 = 0.f, a2 = 0.f;
        if (lane < 16) {
            a0 = rs[lane][0]; a1 = rs[lane][1]; a2 = rs[lane][2];
        }
        // t-count: popc over the 8 center ballot rows (64 words, 2 per lane)
        int tc = __popc(sbits[KW + (lane >> 3)][1 + (lane & 7)])
               + __popc(sbits[KW + 4 + (lane >> 3)][1 + (lane & 7)]);
        float a3 = (float)tc;
#pragma unroll
        for (int off = 16; off > 0; off >>= 1) {
            a0 += __shfl_down_sync(0xffffffffu, a0, off);
            a1 += __shfl_down_sync(0xffffffffu, a1, off);
            a2 += __shfl_down_sync(0xffffffffu, a2, off);
            a3 += __shfl_down_sync(0xffffffffu, a3, off);
        }
        if (lane == 0) {
            d_partials[blk][0] = (double)a0; d_partials[blk][1] = (double)a1;
            d_partials[blk][2] = (double)a2; d_partials[blk][3] = (double)a3;
            __threadfence();
            const int old = atomicAdd(&g_fin, 1);
            s_last = (old == NBLK - 1);
        }
    }
    __syncthreads();
    if (!s_last) return;

    // ---- last block: deterministic finalize --------------------------------
    __threadfence();
    if (warp < 8) {
        const int img = warp;              // one warp per image (32 partials)
        const int s = img * 32 + lane;
        double v0 = d_partials[s][0];
        double v1 = d_partials[s][1];
        double v2 = d_partials[s][2];
        double v3 = d_partials[s][3];
#pragma unroll
        for (int off = 16; off > 0; off >>= 1) {
            v0 += __shfl_down_sync(0xffffffffu, v0, off);
            v1 += __shfl_down_sync(0xffffffffu, v1, off);
            v2 += __shfl_down_sync(0xffffffffu, v2, off);
            v3 += __shfl_down_sync(0xffffffffu, v3, off);
        }
        if (lane == 0) {
            const double eps = 1e-6;
            fg[img][0] = v0;                                       // boundary sum
            fg[img][1] = 1.0 - (2.0 * v1 + eps) / (v2 + v3 + eps); // dice term
        }
    }
    __syncthreads();
    if (tid == 0) {
        double bl = 0.0, dl = 0.0;
#pragma unroll
        for (int i = 0; i < BB; ++i) { bl += fg[i][0]; dl += fg[i][1]; }
        dl /= (double)BB;
        bl /= (double)(BB * HH * WW);
        out[0] = (float)(dl + bl);  // ALPHA = BETA = 1
        g_fin = 0;                  // reset for next (graph) replay
        __threadfence();
    }
}

// ---------------------------------------------------------------------------
extern "C" void kernel_launch(void* const* d_in, const int* in_sizes, int n_in,
                              void* d_out, int out_size) {
    const float* pred   = (const float*)d_in[0];
    const float* target = (const float*)d_in[1];
    const int*   fl     = (const int*)d_in[2];
    float* out = (float*)d_out;

    fused<<<NBLK, NTH>>>(pred, target, fl, out);
}